// round 9
// baseline (speedup 1.0000x reference)
#include <cuda_runtime.h>
#include <cstdint>
#include <math.h>

#define BB 32
#define TT 2048
#define FF 64
#define HH 256
#define GG 768
#define MTOT (BB*TT)

typedef unsigned long long u64;

// scratch (static device arrays: the sanctioned no-alloc workaround)
__device__ float g_xn[(size_t)MTOT*FF];
__device__ float g_xb[(size_t)MTOT*GG];
__device__ float g_h1[(size_t)MTOT*HH];
__device__ float g_h2[BB*HH];

__device__ __forceinline__ u64 ffma2(u64 a, u64 b, u64 c) {
    u64 d;
    asm("fma.rn.f32x2 %0, %1, %2, %3;" : "=l"(d) : "l"(a), "l"(b), "l"(c));
    return d;
}
__device__ __forceinline__ u64 addf2(u64 a, u64 b) {
    u64 d;
    asm("add.rn.f32x2 %0, %1, %2;" : "=l"(d) : "l"(a), "l"(b));
    return d;
}
__device__ __forceinline__ u64 pack2(float x, float y) {
    u64 d;
    asm("mov.b64 %0, {%1, %2};" : "=l"(d) : "f"(x), "f"(y));
    return d;
}
__device__ __forceinline__ void unpack2(u64 v, float& lo, float& hi) {
    asm("mov.b64 {%0, %1}, %2;" : "=f"(lo), "=f"(hi) : "l"(v));
}
__device__ __forceinline__ uint32_t smem_u32(const void* p) {
    return (uint32_t)__cvta_generic_to_shared(p);
}

#define MBAR_INIT(addr, cnt) \
    asm volatile("mbarrier.init.shared.b64 [%0], %1;" :: "r"(addr), "r"(cnt) : "memory")
#define MBAR_EXPECT_TX(addr, bytes) \
    asm volatile("mbarrier.arrive.expect_tx.shared.b64 _, [%0], %1;" :: "r"(addr), "r"(bytes) : "memory")
#define MBAR_WAIT_PARITY(addr, par) do { \
    uint32_t _done = 0; \
    while (!_done) { \
        asm volatile("{\n\t.reg .pred P;\n\t" \
            "mbarrier.try_wait.parity.acquire.cta.shared::cta.b64 P, [%1], %2, 0x989680;\n\t" \
            "selp.b32 %0, 1, 0, P;\n\t}" \
            : "=r"(_done) : "r"(addr), "r"(par) : "memory"); \
    } } while (0)
#define ST_ASYNC_F32(raddr, val, rbar) \
    asm volatile("st.async.shared::cluster.mbarrier::complete_tx::bytes.b32 [%0], %1, [%2];" \
        :: "r"(raddr), "r"(val), "r"(rbar) : "memory")

// ---------------- LayerNorm: one warp per 64-feature row ----------------
__global__ void __launch_bounds__(256) ln_kernel(const float* __restrict__ x,
        const float* __restrict__ gamma, const float* __restrict__ beta,
        float* __restrict__ xn)
{
    int row  = blockIdx.x * 8 + (threadIdx.x >> 5);
    int lane = threadIdx.x & 31;
    const float* xr = x + (size_t)row * FF;
    float v0 = xr[lane], v1 = xr[lane + 32];
    float s = v0 + v1;
    #pragma unroll
    for (int o = 16; o > 0; o >>= 1) s += __shfl_xor_sync(0xffffffffu, s, o);
    float mu = s * (1.f / FF);
    float d0 = v0 - mu, d1 = v1 - mu;
    float q = d0 * d0 + d1 * d1;
    #pragma unroll
    for (int o = 16; o > 0; o >>= 1) q += __shfl_xor_sync(0xffffffffu, q, o);
    float inv = rsqrtf(q * (1.f / FF) + 1e-3f);
    float* orow = xn + (size_t)row * FF;
    orow[lane]      = d0 * inv * gamma[lane]      + beta[lane];
    orow[lane + 32] = d1 * inv * gamma[lane + 32] + beta[lane + 32];
}

// ---- GEMM + bias: 128x128 tile, BK=16, 8x8 microtile, f32x2 FMA,
// ---- double-buffered SMEM (unchanged from R8: 548us) ----
__global__ void __launch_bounds__(256) gemm_bias(const float* __restrict__ A,
        const float* __restrict__ B, const float* __restrict__ bias,
        float* __restrict__ C, int M, int N, int K)
{
    __shared__ __align__(16) float As[2][16][132];
    __shared__ __align__(16) float Bs[2][16][128];
    const int tid = threadIdx.x;
    const int bn = blockIdx.x * 128, bm = blockIdx.y * 128;
    const int arow = tid >> 2, ak = (tid & 3) << 2;
    const int brow = tid >> 4, bc = (tid & 15) << 3;
    const int rm   = (tid >> 4) << 3, rn = (tid & 15) << 3;

    u64 c2[8][4];
    #pragma unroll
    for (int i = 0; i < 8; ++i)
        #pragma unroll
        for (int j = 0; j < 4; ++j) c2[i][j] = 0ull;

    const float* Ap0 = A + (size_t)(bm + arow) * K + ak;
    const float* Ap1 = A + (size_t)(bm + arow + 64) * K + ak;
    const float* Bp0 = B + (size_t)brow * N + bn + bc;

    float4 a0 = *(const float4*)(Ap0);
    float4 a1 = *(const float4*)(Ap1);
    float4 b0 = *(const float4*)(Bp0);
    float4 b1 = *(const float4*)(Bp0 + 4);
    {
        As[0][ak + 0][arow] = a0.x; As[0][ak + 1][arow] = a0.y;
        As[0][ak + 2][arow] = a0.z; As[0][ak + 3][arow] = a0.w;
        As[0][ak + 0][arow + 64] = a1.x; As[0][ak + 1][arow + 64] = a1.y;
        As[0][ak + 2][arow + 64] = a1.z; As[0][ak + 3][arow + 64] = a1.w;
        *(float4*)&Bs[0][brow][bc]     = b0;
        *(float4*)&Bs[0][brow][bc + 4] = b1;
    }
    __syncthreads();

    for (int k0 = 0; k0 < K; k0 += 16) {
        const int cur = (k0 >> 4) & 1, nxt = cur ^ 1;
        const bool more = (k0 + 16) < K;
        if (more) {
            a0 = *(const float4*)(Ap0 + k0 + 16);
            a1 = *(const float4*)(Ap1 + k0 + 16);
            b0 = *(const float4*)(Bp0 + (size_t)(k0 + 16) * N);
            b1 = *(const float4*)(Bp0 + (size_t)(k0 + 16) * N + 4);
        }
        #pragma unroll
        for (int k = 0; k < 16; ++k) {
            float4 x0 = *(const float4*)&As[cur][k][rm];
            float4 x1 = *(const float4*)&As[cur][k][rm + 4];
            ulonglong2 q0 = *(const ulonglong2*)&Bs[cur][k][rn];
            ulonglong2 q1 = *(const ulonglong2*)&Bs[cur][k][rn + 4];
            float am[8] = {x0.x, x0.y, x0.z, x0.w, x1.x, x1.y, x1.z, x1.w};
            #pragma unroll
            for (int i = 0; i < 8; ++i) {
                u64 aa = pack2(am[i], am[i]);
                c2[i][0] = ffma2(aa, q0.x, c2[i][0]);
                c2[i][1] = ffma2(aa, q0.y, c2[i][1]);
                c2[i][2] = ffma2(aa, q1.x, c2[i][2]);
                c2[i][3] = ffma2(aa, q1.y, c2[i][3]);
            }
        }
        if (more) {
            As[nxt][ak + 0][arow] = a0.x; As[nxt][ak + 1][arow] = a0.y;
            As[nxt][ak + 2][arow] = a0.z; As[nxt][ak + 3][arow] = a0.w;
            As[nxt][ak + 0][arow + 64] = a1.x; As[nxt][ak + 1][arow + 64] = a1.y;
            As[nxt][ak + 2][arow + 64] = a1.z; As[nxt][ak + 3][arow + 64] = a1.w;
            *(float4*)&Bs[nxt][brow][bc]     = b0;
            *(float4*)&Bs[nxt][brow][bc + 4] = b1;
            __syncthreads();
        }
    }
    float4 bv0 = *(const float4*)(bias + bn + rn);
    float4 bv1 = *(const float4*)(bias + bn + rn + 4);
    #pragma unroll
    for (int i = 0; i < 8; ++i) {
        float o[8];
        unpack2(c2[i][0], o[0], o[1]);
        unpack2(c2[i][1], o[2], o[3]);
        unpack2(c2[i][2], o[4], o[5]);
        unpack2(c2[i][3], o[6], o[7]);
        float4 w0 = {o[0] + bv0.x, o[1] + bv0.y, o[2] + bv0.z, o[3] + bv0.w};
        float4 w1 = {o[4] + bv1.x, o[5] + bv1.y, o[6] + bv1.z, o[7] + bv1.w};
        float* cp = C + (size_t)(bm + rm + i) * N + bn + rn;
        *(float4*)cp = w0;
        *(float4*)(cp + 4) = w1;
    }
}

// --------- Persistent GRU: 32 clusters x 4 CTAs, 1 cluster/batch ---------
// Warp-autonomous layout: warp w owns output columns 8w..8w+8 over FULL
// K=256. Lane (c = lane>>2, q = lane&3): column 8w+c, k subset
// {blk + q*4 + 16m + i}. 96 weight u64/thread (all compile-time indexed).
// In-warp split-k reduce (2 shuffle rounds over q). Gate tail on 8 lanes of
// every warp. ALL 256 h values travel via st.async (3 peers + self) with
// 2 parity-alternating tx-mbarriers, expect_tx = 1024 B. No __syncthreads
// in the loop: the mbar wait is the only synchronization.
__global__ void __launch_bounds__(256, 1) __cluster_dims__(4, 1, 1)
gru_kernel(const float* __restrict__ xb, const float* __restrict__ rk,
           const float* __restrict__ brec, float* __restrict__ seqout,
           float* __restrict__ hfinal, int write_seq)
{
    __shared__ __align__(16) float hsm[512];   // 2 x 256 h double-buffer
    __shared__ float brs[192];                 // [3][64]
    __shared__ __align__(8) u64 mbars[2];      // step-parity tx barriers

    const int tid   = threadIdx.x;
    const int rank  = blockIdx.x & 3;
    const int batch = blockIdx.x >> 2;
    const int jbase = rank * 64;
    const int w     = tid >> 5;
    const int lane  = tid & 31;
    const int q     = lane & 3;     // k-quarter within 16-chunks
    const int c     = lane >> 2;    // column within warp's 8
    const int jcol  = w * 8 + c;    // local output column 0..63

    int blk[4];
    #pragma unroll
    for (int p = 0; p < 4; ++p) blk[p] = ((rank + p) & 3) * 64;

    // weights: w2[(p*4+m)*2+pair][g] = rk[blk[p]+q*4+16m+{2pair,2pair+1}][g*256+jbase+jcol]
    u64 w2[32][3];
    #pragma unroll
    for (int p = 0; p < 4; ++p)
        #pragma unroll
        for (int m = 0; m < 4; ++m) {
            const int k0 = blk[p] + q * 4 + m * 16;
            #pragma unroll
            for (int g = 0; g < 3; ++g) {
                const int col = g * 256 + jbase + jcol;
                w2[(p * 4 + m) * 2 + 0][g] =
                    pack2(rk[(size_t)(k0 + 0) * GG + col], rk[(size_t)(k0 + 1) * GG + col]);
                w2[(p * 4 + m) * 2 + 1][g] =
                    pack2(rk[(size_t)(k0 + 2) * GG + col], rk[(size_t)(k0 + 3) * GG + col]);
            }
        }

    if (tid < 192) brs[tid] = brec[(tid >> 6) * 256 + jbase + (tid & 63)];
    hsm[tid] = 0.f; hsm[256 + tid] = 0.f;

    uint32_t mb[2] = { smem_u32(&mbars[0]), smem_u32(&mbars[1]) };
    if (tid == 0) { MBAR_INIT(mb[0], 1); MBAR_INIT(mb[1], 1); }

    // owner lanes (q==0): remote h slots + barriers on all 4 CTAs (incl self)
    uint32_t rem_h[2][4], rem_bar[2][4];
    if (q == 0) {
        #pragma unroll
        for (int b = 0; b < 2; ++b) {
            uint32_t lh = smem_u32(hsm + b * 256 + jbase + jcol);
            #pragma unroll
            for (int p = 0; p < 4; ++p) {
                uint32_t rh, rb;
                asm("mapa.shared::cluster.u32 %0, %1, %2;" : "=r"(rh) : "r"(lh), "r"(p));
                asm("mapa.shared::cluster.u32 %0, %1, %2;" : "=r"(rb) : "r"(mb[b]), "r"(p));
                rem_h[b][p] = rh; rem_bar[b][p] = rb;
            }
        }
    }
    __syncthreads();
    // mbarriers + zeroed h visible cluster-wide before any st.async
    asm volatile("barrier.cluster.arrive.aligned;" ::: "memory");
    asm volatile("barrier.cluster.wait.aligned;" ::: "memory");
    if (tid == 0) { MBAR_EXPECT_TX(mb[0], 1024); MBAR_EXPECT_TX(mb[1], 1024); }
    __syncthreads();  // arms ordered before any warp's step-0 pushes

    const float* xrow = xb + (size_t)batch * TT * GG;
    float* srow = seqout + (size_t)batch * TT * HH;
    float hprev = 0.f;   // owner's own-column h (register-resident)

    for (int t = 0; t < TT; ++t) {
        const float* cur = hsm + ((t & 1) << 8);
        const int    nb  = (t & 1) ^ 1;

        float xz = 0.f, xr_ = 0.f, xh = 0.f;
        if (q == 0) {
            const float* xp = xrow + (size_t)t * GG + jbase + jcol;
            xz = __ldg(xp); xr_ = __ldg(xp + 256); xh = __ldg(xp + 512);
        }

        if (t > 0) {
            MBAR_WAIT_PARITY(mb[(t - 1) & 1], ((t - 1) >> 1) & 1);
            if (w == 0) {
                if (lane == 0 && t <= TT - 3) MBAR_EXPECT_TX(mb[(t + 1) & 1], 1024);
                __syncwarp();   // order warp0's pushes after the re-arm
            }
        }

        u64 a2[3] = {0ull, 0ull, 0ull};
        #pragma unroll
        for (int p = 0; p < 4; ++p)
            #pragma unroll
            for (int m = 0; m < 4; ++m) {
                float4 h4 = *(const float4*)(cur + blk[p] + q * 4 + m * 16);
                u64 h01 = pack2(h4.x, h4.y);
                u64 h23 = pack2(h4.z, h4.w);
                const int base = (p * 4 + m) * 2;
                a2[0] = ffma2(h01, w2[base][0], a2[0]);
                a2[1] = ffma2(h01, w2[base][1], a2[1]);
                a2[2] = ffma2(h01, w2[base][2], a2[2]);
                a2[0] = ffma2(h23, w2[base + 1][0], a2[0]);
                a2[1] = ffma2(h23, w2[base + 1][1], a2[1]);
                a2[2] = ffma2(h23, w2[base + 1][2], a2[2]);
            }

        // in-warp reduce over the 4 q-lanes of each column group
        #pragma unroll
        for (int g = 0; g < 3; ++g) {
            a2[g] = addf2(a2[g], __shfl_xor_sync(0xffffffffu, a2[g], 1));
            a2[g] = addf2(a2[g], __shfl_xor_sync(0xffffffffu, a2[g], 2));
        }

        if (q == 0) {
            float lo0, hi0, lo1, hi1, lo2, hi2;
            unpack2(a2[0], lo0, hi0);
            unpack2(a2[1], lo1, hi1);
            unpack2(a2[2], lo2, hi2);
            float gz = (lo0 + hi0) + brs[jcol]       + xz;
            float gr = (lo1 + hi1) + brs[64 + jcol]  + xr_;
            float gh = (lo2 + hi2) + brs[128 + jcol];
            float z  = __fdividef(1.f, 1.f + __expf(-gz));
            float r  = __fdividef(1.f, 1.f + __expf(-gr));
            float u  = xh + r * gh;
            float th = __fdividef(2.f, 1.f + __expf(-2.f * u)) - 1.f;
            float hn = z * hprev + (1.f - z) * th;
            hprev = hn;
            if (t < TT - 1) {
                uint32_t hb = __float_as_uint(hn);
                ST_ASYNC_F32(rem_h[nb][0], hb, rem_bar[t & 1][0]);
                ST_ASYNC_F32(rem_h[nb][1], hb, rem_bar[t & 1][1]);
                ST_ASYNC_F32(rem_h[nb][2], hb, rem_bar[t & 1][2]);
                ST_ASYNC_F32(rem_h[nb][3], hb, rem_bar[t & 1][3]);
            }
            if (write_seq) srow[(size_t)t * HH + jbase + jcol] = hn;
            else if (t == TT - 1) hfinal[batch * HH + jbase + jcol] = hn;
        }
    }
}

// ---------------- Dense: out[32,64] = h2 @ wd + bd ----------------
__global__ void __launch_bounds__(256) dense_kernel(const float* __restrict__ h2,
        const float* __restrict__ wd, const float* __restrict__ bd,
        float* __restrict__ out)
{
    int o = blockIdx.x * 256 + threadIdx.x;
    int b = o >> 6, j = o & 63;
    float s = bd[j];
    for (int k = 0; k < HH; ++k) s += h2[b * HH + k] * wd[k * 64 + j];
    out[o] = s;
}

extern "C" void kernel_launch(void* const* d_in, const int* in_sizes, int n_in,
                              void* d_out, int out_size) {
    const float* x     = (const float*)d_in[0];
    const float* gamma = (const float*)d_in[1];
    const float* beta  = (const float*)d_in[2];
    const float* k1    = (const float*)d_in[3];
    const float* rk1   = (const float*)d_in[4];
    const float* b1    = (const float*)d_in[5];
    const float* k2    = (const float*)d_in[6];
    const float* rk2   = (const float*)d_in[7];
    const float* b2    = (const float*)d_in[8];
    const float* wd    = (const float*)d_in[9];
    const float* bd    = (const float*)d_in[10];
    float* out = (float*)d_out;

    float *xn, *xbuf, *h1, *h2;
    cudaGetSymbolAddress((void**)&xn,   g_xn);
    cudaGetSymbolAddress((void**)&xbuf, g_xb);
    cudaGetSymbolAddress((void**)&h1,   g_h1);
    cudaGetSymbolAddress((void**)&h2,   g_h2);

    ln_kernel<<<MTOT / 8, 256>>>(x, gamma, beta, xn);
    gemm_bias<<<dim3(GG / 128, MTOT / 128), 256>>>(xn, k1, b1, xbuf, MTOT, GG, FF);
    gru_kernel<<<128, 256>>>(xbuf, rk1, b1 + GG, h1, h2, 1);
    gemm_bias<<<dim3(GG / 128, MTOT / 128), 256>>>(h1, k2, b2, xbuf, MTOT, GG, HH);
    gru_kernel<<<128, 256>>>(xbuf, rk2, b2 + GG, h1, h2, 0);
    dense_kernel<<<(BB * 64) / 256, 256>>>(h2, wd, bd, out);
}